// round 1
// baseline (speedup 1.0000x reference)
#include <cuda_runtime.h>
#include <cstdint>

#define HEADS 6
#define NTOK  64
#define DIM   96
#define HD    16
#define NW    512

// Precomputed relative-position bias, (H, N, N) layout.
__device__ float g_bias[HEADS * NTOK * NTOK];

__global__ void bias_prep_kernel(const float* __restrict__ rpb,
                                 const int* __restrict__ ridx) {
    int i = blockIdx.x * blockDim.x + threadIdx.x;   // 0 .. 6*64*64-1
    if (i < HEADS * NTOK * NTOK) {
        int h  = i / (NTOK * NTOK);
        int nm = i % (NTOK * NTOK);
        g_bias[i] = rpb[ridx[nm] * HEADS + h];
    }
}

// One CTA per window. 256 threads = (ty 0..15) x (tx 0..15).
// SMEM layout (floats):
//   xs [0,      6144)  : x tile 64x96, later reused as attention output o
//   wa [6144,   9216)  : weight chunk 32x96 (GEMM stages) / attn 32x64 (attn stage)
//   qs [9216,  15360)  : Q 64x96 (pre-scaled)
//   ks [15360, 21568)  : K 64x97 (padded -> conflict-free K^T reads)
//   vs [21568, 27712)  : V 64x96
#define SMEM_FLOATS 27712

__global__ __launch_bounds__(256, 2)
void win_attn_kernel(const float* __restrict__ x,
                     const float* __restrict__ mask,
                     const float* __restrict__ qkv_w,
                     const float* __restrict__ qkv_b,
                     const float* __restrict__ proj_w,
                     const float* __restrict__ proj_b,
                     float* __restrict__ out,
                     int n_windows)
{
    extern __shared__ float sm[];
    float* xs = sm;
    float* wa = sm + 6144;
    float* qs = sm + 9216;
    float* ks = sm + 15360;
    float* vs = sm + 21568;

    const int tid = threadIdx.x;
    const int tx  = tid & 15;
    const int ty  = tid >> 4;
    const int b   = blockIdx.x;
    if (b >= n_windows) return;

    // ---- load x tile (64x96 floats = 1536 float4) ----
    {
        const float4* xg = reinterpret_cast<const float4*>(x + (size_t)b * NTOK * DIM);
        float4* xl = reinterpret_cast<float4*>(xs);
        #pragma unroll
        for (int u = 0; u < 6; ++u) xl[tid + u * 256] = xg[tid + u * 256];
    }
    __syncthreads();

    // =========================== QKV GEMM ===========================
    // C[64][96] per pass p: rows r_i = ty + i*16, cols c_j = tx + j*16.
    #pragma unroll 1
    for (int p = 0; p < 3; ++p) {
        float acc[4][6];
        #pragma unroll
        for (int j = 0; j < 6; ++j) {
            float bj = qkv_b[p * 96 + tx + j * 16];
            #pragma unroll
            for (int i = 0; i < 4; ++i) acc[i][j] = bj;
        }

        #pragma unroll 1
        for (int kb = 0; kb < 96; kb += 32) {
            __syncthreads();   // previous chunk fully consumed
            // stage 32x96 weight chunk into SMEM (768 float4)
            {
                const float* wsrc = qkv_w + (size_t)kb * 288 + p * 96;
                #pragma unroll
                for (int u = 0; u < 3; ++u) {
                    int e = tid + u * 256;
                    int r = e / 24, c = e % 24;
                    reinterpret_cast<float4*>(wa)[e] =
                        *reinterpret_cast<const float4*>(wsrc + r * 288 + c * 4);
                }
            }
            __syncthreads();

            #pragma unroll
            for (int k4 = 0; k4 < 8; ++k4) {
                float4 xr[4];
                #pragma unroll
                for (int i = 0; i < 4; ++i)
                    xr[i] = *reinterpret_cast<const float4*>(
                        &xs[(ty + i * 16) * 96 + kb + k4 * 4]);
                #pragma unroll
                for (int t = 0; t < 4; ++t) {
                    float wv[6];
                    #pragma unroll
                    for (int j = 0; j < 6; ++j)
                        wv[j] = wa[(k4 * 4 + t) * 96 + tx + j * 16];
                    #pragma unroll
                    for (int i = 0; i < 4; ++i) {
                        float xv = (t == 0) ? xr[i].x : (t == 1) ? xr[i].y
                                 : (t == 2) ? xr[i].z : xr[i].w;
                        #pragma unroll
                        for (int j = 0; j < 6; ++j)
                            acc[i][j] = fmaf(xv, wv[j], acc[i][j]);
                    }
                }
            }
        }

        float* dst      = (p == 0) ? qs : (p == 1) ? ks : vs;
        const int strd  = (p == 1) ? 97 : 96;
        const float scl = (p == 0) ? 0.25f : 1.0f;   // hd^-0.5 = 16^-0.5
        #pragma unroll
        for (int i = 0; i < 4; ++i)
            #pragma unroll
            for (int j = 0; j < 6; ++j)
                dst[(ty + i * 16) * strd + tx + j * 16] = acc[i][j] * scl;
    }
    __syncthreads();

    // =========================== attention ===========================
    const float* mp = mask + (size_t)(b % NW) * NTOK * NTOK;

    #pragma unroll 1
    for (int h = 0; h < HEADS; ++h) {
        const int cb = h * HD;
        #pragma unroll 1
        for (int nh = 0; nh < 2; ++nh) {
            const int n0 = nh * 32;

            // ---- QK^T: thread -> rows n0+ty*2+{0,1}, cols tx+{0..3}*16 ----
            float a2[2][4] = {{0.f,0.f,0.f,0.f},{0.f,0.f,0.f,0.f}};
            #pragma unroll
            for (int d = 0; d < 16; ++d) {
                float qv[2], kv[4];
                #pragma unroll
                for (int i = 0; i < 2; ++i)
                    qv[i] = qs[(n0 + ty * 2 + i) * 96 + cb + d];
                #pragma unroll
                for (int j = 0; j < 4; ++j)
                    kv[j] = ks[(tx + j * 16) * 97 + cb + d];
                #pragma unroll
                for (int i = 0; i < 2; ++i)
                    #pragma unroll
                    for (int j = 0; j < 4; ++j)
                        a2[i][j] = fmaf(qv[i], kv[j], a2[i][j]);
            }
            #pragma unroll
            for (int i = 0; i < 2; ++i) {
                int n = n0 + ty * 2 + i;
                #pragma unroll
                for (int j = 0; j < 4; ++j) {
                    int m = tx + j * 16;
                    wa[(n - n0) * 64 + m] =
                        a2[i][j] + g_bias[h * 4096 + n * 64 + m] + mp[n * 64 + m];
                }
            }
            __syncthreads();

            // ---- softmax: 32 rows, 8 threads/row, 8 cols/thread ----
            {
                int r  = tid >> 3;
                int c0 = (tid & 7) * 8;
                float* row = wa + r * 64 + c0;
                float4 va = reinterpret_cast<float4*>(row)[0];
                float4 vb = reinterpret_cast<float4*>(row)[1];
                float mx = fmaxf(fmaxf(fmaxf(va.x, va.y), fmaxf(va.z, va.w)),
                                 fmaxf(fmaxf(vb.x, vb.y), fmaxf(vb.z, vb.w)));
                #pragma unroll
                for (int o = 4; o > 0; o >>= 1)
                    mx = fmaxf(mx, __shfl_xor_sync(0xffffffffu, mx, o, 8));
                va.x = __expf(va.x - mx); va.y = __expf(va.y - mx);
                va.z = __expf(va.z - mx); va.w = __expf(va.w - mx);
                vb.x = __expf(vb.x - mx); vb.y = __expf(vb.y - mx);
                vb.z = __expf(vb.z - mx); vb.w = __expf(vb.w - mx);
                float s = va.x + va.y + va.z + va.w + vb.x + vb.y + vb.z + vb.w;
                #pragma unroll
                for (int o = 4; o > 0; o >>= 1)
                    s += __shfl_xor_sync(0xffffffffu, s, o, 8);
                float inv = 1.0f / s;
                va.x *= inv; va.y *= inv; va.z *= inv; va.w *= inv;
                vb.x *= inv; vb.y *= inv; vb.z *= inv; vb.w *= inv;
                reinterpret_cast<float4*>(row)[0] = va;
                reinterpret_cast<float4*>(row)[1] = vb;
            }
            __syncthreads();

            // ---- PV: thread -> rows n0+ty*2+{0,1}, col d = tx ----
            {
                float oa0 = 0.f, oa1 = 0.f;
                #pragma unroll 4
                for (int m = 0; m < 64; ++m) {
                    float vv = vs[m * 96 + cb + tx];
                    oa0 = fmaf(wa[(ty * 2 + 0) * 64 + m], vv, oa0);
                    oa1 = fmaf(wa[(ty * 2 + 1) * 64 + m], vv, oa1);
                }
                xs[(n0 + ty * 2 + 0) * 96 + cb + tx] = oa0;   // o reuses xs
                xs[(n0 + ty * 2 + 1) * 96 + cb + tx] = oa1;
            }
            __syncthreads();
        }
    }

    // =========================== proj GEMM ===========================
    {
        float acc[4][6];
        #pragma unroll
        for (int j = 0; j < 6; ++j) {
            float bj = proj_b[tx + j * 16];
            #pragma unroll
            for (int i = 0; i < 4; ++i) acc[i][j] = bj;
        }

        #pragma unroll 1
        for (int kb = 0; kb < 96; kb += 32) {
            __syncthreads();
            #pragma unroll
            for (int u = 0; u < 3; ++u) {
                int e = tid + u * 256;
                int r = e / 24, c = e % 24;
                reinterpret_cast<float4*>(wa)[e] =
                    *reinterpret_cast<const float4*>(proj_w + (size_t)(kb + r) * 96 + c * 4);
            }
            __syncthreads();

            #pragma unroll
            for (int k4 = 0; k4 < 8; ++k4) {
                float4 xr[4];
                #pragma unroll
                for (int i = 0; i < 4; ++i)
                    xr[i] = *reinterpret_cast<const float4*>(
                        &xs[(ty + i * 16) * 96 + kb + k4 * 4]);
                #pragma unroll
                for (int t = 0; t < 4; ++t) {
                    float wv[6];
                    #pragma unroll
                    for (int j = 0; j < 6; ++j)
                        wv[j] = wa[(k4 * 4 + t) * 96 + tx + j * 16];
                    #pragma unroll
                    for (int i = 0; i < 4; ++i) {
                        float xv = (t == 0) ? xr[i].x : (t == 1) ? xr[i].y
                                 : (t == 2) ? xr[i].z : xr[i].w;
                        #pragma unroll
                        for (int j = 0; j < 6; ++j)
                            acc[i][j] = fmaf(xv, wv[j], acc[i][j]);
                    }
                }
            }
        }

        float* og = out + (size_t)b * NTOK * DIM;
        #pragma unroll
        for (int i = 0; i < 4; ++i)
            #pragma unroll
            for (int j = 0; j < 6; ++j)
                og[(ty + i * 16) * 96 + tx + j * 16] = acc[i][j];
    }
}

extern "C" void kernel_launch(void* const* d_in, const int* in_sizes, int n_in,
                              void* d_out, int out_size)
{
    const float* x      = (const float*)d_in[0];
    const float* mask   = (const float*)d_in[1];
    const float* qkv_w  = (const float*)d_in[2];
    const float* qkv_b  = (const float*)d_in[3];
    const float* proj_w = (const float*)d_in[4];
    const float* proj_b = (const float*)d_in[5];
    const float* rpb    = (const float*)d_in[6];
    const int*   ridx   = (const int*)d_in[7];
    float* out = (float*)d_out;

    const int n_windows = in_sizes[0] / (NTOK * DIM);   // 8192

    static bool attr_set = false;
    // cudaFuncSetAttribute is not a stream operation; safe during capture.
    cudaFuncSetAttribute(win_attn_kernel,
                         cudaFuncAttributeMaxDynamicSharedMemorySize,
                         SMEM_FLOATS * sizeof(float));
    (void)attr_set;

    // 1) gather relative-position bias into (H,N,N) device-global table
    bias_prep_kernel<<<96, 256>>>(rpb, ridx);
    // 2) fused window attention, one CTA per window
    win_attn_kernel<<<n_windows, 256, SMEM_FLOATS * sizeof(float)>>>(
        x, mask, qkv_w, qkv_b, proj_w, proj_b, out, n_windows);
}